// round 4
// baseline (speedup 1.0000x reference)
#include <cuda_runtime.h>

// GRU: B=64, T=1024, INPUT=512, HIDDEN=1024
// out = (B,T,H) fp32 followed by h_n = (1,B,H) fp32.

#define Bdim 64
#define Tdim 1024
#define Idim 512
#define Hdim 1024
#define NCTA 64      // persistent scan CTAs (<= SM count, 1 CTA/SM -> co-resident)
#define SW   1028    // smem row stride (words) for weight tiles: 1028 % 32 == 4 -> conflict-free frags
#define HSW  68      // smem row stride (words) for h tile: 68 % 32 == 4

// ------------------------- device scratch (static; no runtime alloc) -------
static __device__ float g_xg[3ull * Tdim * Bdim * Hdim];  // [gate][t][b][h], bias included
static __device__ float g_h [Bdim * Hdim];
static __device__ float g_z [Bdim * Hdim];
static __device__ float g_rh[Bdim * Hdim];
static __device__ unsigned g_bar_count;   // zero-init; returns to 0 after every barrier
static __device__ unsigned g_bar_gen;     // monotonically increasing; equality-spin is wrap-safe

__device__ __forceinline__ unsigned f2tf(float f) {
    unsigned u;
    asm("cvt.rna.tf32.f32 %0, %1;" : "=r"(u) : "f"(f));
    return u;
}

// D += A(16x8,row) * B(8x8,col)   tf32 -> f32
__device__ __forceinline__ void mma8(float* d, const unsigned* a, unsigned b0, unsigned b1) {
    asm volatile(
        "mma.sync.aligned.m16n8k8.row.col.f32.tf32.tf32.f32 "
        "{%0,%1,%2,%3}, {%4,%5,%6,%7}, {%8,%9}, {%0,%1,%2,%3};\n"
        : "+f"(d[0]), "+f"(d[1]), "+f"(d[2]), "+f"(d[3])
        : "r"(a[0]), "r"(a[1]), "r"(a[2]), "r"(a[3]), "r"(b0), "r"(b1));
}

// Grid-wide barrier for NCTA co-resident CTAs. Generation-counting, reusable
// across graph replays (gen persists and is compared by equality).
__device__ __forceinline__ void grid_barrier(unsigned* gen) {
    __threadfence();                // publish this thread's prior writes
    __syncthreads();
    if (threadIdx.x == 0) {
        unsigned old = atomicAdd(&g_bar_count, 1u);
        if (old == NCTA - 1) {
            atomicExch(&g_bar_count, 0u);
            __threadfence();
            atomicAdd(&g_bar_gen, 1u);
        } else {
            while (*(volatile unsigned*)&g_bar_gen == *gen) {
                __nanosleep(64);
            }
        }
        __threadfence();
    }
    __syncthreads();
    (*gen)++;
}

// ---------------------------------------------------------------------------
// Input projection: for gate g, xg[g][t][b][:] = x[b][t][:] @ W_g^T + b_g
// M = B*T = 65536, N = 1024, K = 512. CTA tile 128x64, 256 threads.
// ---------------------------------------------------------------------------
__global__ __launch_bounds__(256, 2) void proj_kernel(
    const float* __restrict__ x,
    const float* __restrict__ Wz, const float* __restrict__ bz,
    const float* __restrict__ Wr, const float* __restrict__ br,
    const float* __restrict__ Wh, const float* __restrict__ bh)
{
    const int gate = blockIdx.z;
    const float* __restrict__ W    = (gate == 0) ? Wz : (gate == 1) ? Wr : Wh;
    const float* __restrict__ bias = (gate == 0) ? bz : (gate == 1) ? br : bh;

    __shared__ unsigned As[128][33];
    __shared__ unsigned Bs[64][33];

    const int tid  = threadIdx.x;
    const int lane = tid & 31;
    const int warp = tid >> 5;
    const int gid  = lane >> 2;
    const int tig  = lane & 3;
    const int wm   = warp >> 1;
    const int wn   = warp & 1;

    const long mbase = (long)blockIdx.x * 128;
    const int  nbase = blockIdx.y * 64;

    const int arow = tid >> 1;
    const int aseg = (tid & 1) * 16;
    const int brow = tid >> 3;
    const int bcol = (tid & 7) * 4;

    float acc[2][4][4];
    #pragma unroll
    for (int i = 0; i < 2; i++)
        #pragma unroll
        for (int j = 0; j < 4; j++)
            #pragma unroll
            for (int k = 0; k < 4; k++) acc[i][j][k] = 0.f;

    float4 aR[4], bR[2];
    {
        const float* ap = x + (mbase + arow) * Idim + aseg;
        #pragma unroll
        for (int q = 0; q < 4; q++) aR[q] = reinterpret_cast<const float4*>(ap)[q];
        #pragma unroll
        for (int p = 0; p < 2; p++)
            bR[p] = *reinterpret_cast<const float4*>(W + (long)(nbase + brow + p * 32) * Idim + bcol);
    }

    for (int kc = 0; kc < Idim; kc += 32) {
        #pragma unroll
        for (int q = 0; q < 4; q++) {
            As[arow][aseg + q * 4 + 0] = f2tf(aR[q].x);
            As[arow][aseg + q * 4 + 1] = f2tf(aR[q].y);
            As[arow][aseg + q * 4 + 2] = f2tf(aR[q].z);
            As[arow][aseg + q * 4 + 3] = f2tf(aR[q].w);
        }
        #pragma unroll
        for (int p = 0; p < 2; p++) {
            Bs[brow + p * 32][bcol + 0] = f2tf(bR[p].x);
            Bs[brow + p * 32][bcol + 1] = f2tf(bR[p].y);
            Bs[brow + p * 32][bcol + 2] = f2tf(bR[p].z);
            Bs[brow + p * 32][bcol + 3] = f2tf(bR[p].w);
        }
        __syncthreads();

        if (kc + 32 < Idim) {
            const float* ap = x + (mbase + arow) * Idim + (kc + 32) + aseg;
            #pragma unroll
            for (int q = 0; q < 4; q++) aR[q] = reinterpret_cast<const float4*>(ap)[q];
            #pragma unroll
            for (int p = 0; p < 2; p++)
                bR[p] = *reinterpret_cast<const float4*>(W + (long)(nbase + brow + p * 32) * Idim + (kc + 32) + bcol);
        }

        #pragma unroll
        for (int ks = 0; ks < 4; ks++) {
            unsigned afrag[2][4];
            #pragma unroll
            for (int mt = 0; mt < 2; mt++) {
                int r0 = wm * 32 + mt * 16 + gid;
                afrag[mt][0] = As[r0    ][ks * 8 + tig];
                afrag[mt][1] = As[r0 + 8][ks * 8 + tig];
                afrag[mt][2] = As[r0    ][ks * 8 + tig + 4];
                afrag[mt][3] = As[r0 + 8][ks * 8 + tig + 4];
            }
            #pragma unroll
            for (int nt = 0; nt < 4; nt++) {
                int n0 = wn * 32 + nt * 8 + gid;
                unsigned b0 = Bs[n0][ks * 8 + tig];
                unsigned b1 = Bs[n0][ks * 8 + tig + 4];
                mma8(acc[0][nt], afrag[0], b0, b1);
                mma8(acc[1][nt], afrag[1], b0, b1);
            }
        }
        __syncthreads();
    }

    #pragma unroll
    for (int mt = 0; mt < 2; mt++) {
        #pragma unroll
        for (int nt = 0; nt < 4; nt++) {
            #pragma unroll
            for (int i = 0; i < 4; i++) {
                int mr = wm * 32 + mt * 16 + gid + ((i >= 2) ? 8 : 0);
                int j  = nbase + wn * 32 + nt * 8 + tig * 2 + (i & 1);
                long m = mbase + mr;
                int b = (int)(m >> 10);   // x rows are (b, t), t fastest (T=1024)
                int t = (int)(m & 1023);
                float v = acc[mt][nt][i] + bias[j];
                g_xg[(((long)gate * Tdim + t) * Bdim + b) * Hdim + j] = v;
            }
        }
    }
}

// ---------------------------------------------------------------------------
// Persistent scan kernel: 64 CTAs, 256 threads each, weights SMEM-resident.
// Phase A (per step): z/r pre-acts.  CTA c<32 -> z cols [32c,32c+32); c>=32 -> r.
// Phase B: h_tilde + state update.   CTA c -> cols [16c, 16c+16).
// 2 grid barriers per step.
// ---------------------------------------------------------------------------
extern __shared__ unsigned smem_u[];

__global__ __launch_bounds__(256, 1) void scan_kernel(
    const float* __restrict__ Uz, const float* __restrict__ Ur,
    const float* __restrict__ Uh, float* __restrict__ out)
{
    unsigned* WA = smem_u;               // 32 x SW  (z or r weight rows, tf32)
    unsigned* WB = WA + 32 * SW;         // 16 x SW  (Uh rows, tf32)
    unsigned* Hs = WB + 16 * SW;         // 64 x HSW (h / rh staging chunk)

    const int c    = blockIdx.x;
    const int tid  = threadIdx.x;
    const int lane = tid & 31;
    const int warp = tid >> 5;
    const int gid  = lane >> 2;
    const int tig  = lane & 3;
    const int wm   = warp >> 1;          // 0..3  m-stripe of 16 batch rows
    const int wn   = warp & 1;           // 0..1  n-half

    const int gate = (c < 32) ? 0 : 1;
    const float* __restrict__ UA = gate ? Ur : Uz;
    const int jbA = (c & 31) * 32;
    const int jbB = c * 16;

    // ---- one-time: load weight slices into SMEM as tf32 ----
    for (int i = tid; i < 32 * (Hdim / 4); i += 256) {
        int r = i >> 8, c4 = (i & 255) * 4;
        float4 v = *reinterpret_cast<const float4*>(UA + (long)(jbA + r) * Hdim + c4);
        uint4 w = { f2tf(v.x), f2tf(v.y), f2tf(v.z), f2tf(v.w) };
        *reinterpret_cast<uint4*>(&WA[r * SW + c4]) = w;
    }
    for (int i = tid; i < 16 * (Hdim / 4); i += 256) {
        int r = i >> 8, c4 = (i & 255) * 4;
        float4 v = *reinterpret_cast<const float4*>(Uh + (long)(jbB + r) * Hdim + c4);
        uint4 w = { f2tf(v.x), f2tf(v.y), f2tf(v.z), f2tf(v.w) };
        *reinterpret_cast<uint4*>(&WB[r * SW + c4]) = w;
    }

    unsigned gen = *(volatile unsigned*)&g_bar_gen;  // stable: no barrier can
    __syncthreads();                                 // complete before all read

    const int arow  = tid >> 2;          // 0..63 (batch row for h staging)
    const int cbase = (tid & 3) * 16;    // 16-col segment within 64-wide chunk

    for (int t = 0; t < Tdim; t++) {
        // ================= Phase A: z / r gates =================
        float accA[2][4];
        #pragma unroll
        for (int nt = 0; nt < 2; nt++)
            #pragma unroll
            for (int i = 0; i < 4; i++) accA[nt][i] = 0.f;

        float4 hr[4];
        {
            const float* p = g_h + arow * Hdim + cbase;
            #pragma unroll
            for (int q = 0; q < 4; q++) hr[q] = reinterpret_cast<const float4*>(p)[q];
        }
        for (int kc = 0; kc < Hdim; kc += 64) {
            #pragma unroll
            for (int q = 0; q < 4; q++) {
                uint4 w = { f2tf(hr[q].x), f2tf(hr[q].y), f2tf(hr[q].z), f2tf(hr[q].w) };
                *reinterpret_cast<uint4*>(&Hs[arow * HSW + cbase + q * 4]) = w;
            }
            __syncthreads();
            if (kc + 64 < Hdim) {
                const float* p = g_h + arow * Hdim + (kc + 64) + cbase;
                #pragma unroll
                for (int q = 0; q < 4; q++) hr[q] = reinterpret_cast<const float4*>(p)[q];
            }
            #pragma unroll
            for (int ks = 0; ks < 8; ks++) {
                int k  = ks * 8 + tig;
                int r0 = (wm * 16 + gid) * HSW;
                unsigned a[4] = { Hs[r0 + k], Hs[r0 + 8 * HSW + k],
                                  Hs[r0 + k + 4], Hs[r0 + 8 * HSW + k + 4] };
                int kk = kc + k;
                #pragma unroll
                for (int nt = 0; nt < 2; nt++) {
                    int n0 = wn * 16 + nt * 8 + gid;
                    mma8(accA[nt], a, WA[n0 * SW + kk], WA[n0 * SW + kk + 4]);
                }
            }
            __syncthreads();
        }
        {
            const float* __restrict__ xg = g_xg + ((long)gate * Tdim + t) * Bdim * Hdim;
            #pragma unroll
            for (int nt = 0; nt < 2; nt++) {
                #pragma unroll
                for (int i = 0; i < 4; i++) {
                    int b = wm * 16 + gid + ((i >= 2) ? 8 : 0);
                    int j = jbA + wn * 16 + nt * 8 + tig * 2 + (i & 1);
                    int idx = b * Hdim + j;
                    float pre = accA[nt][i] + xg[idx];
                    float s = 1.0f / (1.0f + __expf(-pre));
                    if (gate == 0) g_z[idx] = s;
                    else           g_rh[idx] = s * g_h[idx];
                }
            }
        }
        grid_barrier(&gen);

        // ================= Phase B: h_tilde + update =================
        float accB[4] = {0.f, 0.f, 0.f, 0.f};
        {
            const float* p = g_rh + arow * Hdim + cbase;
            #pragma unroll
            for (int q = 0; q < 4; q++) hr[q] = reinterpret_cast<const float4*>(p)[q];
        }
        for (int kc = 0; kc < Hdim; kc += 64) {
            #pragma unroll
            for (int q = 0; q < 4; q++) {
                uint4 w = { f2tf(hr[q].x), f2tf(hr[q].y), f2tf(hr[q].z), f2tf(hr[q].w) };
                *reinterpret_cast<uint4*>(&Hs[arow * HSW + cbase + q * 4]) = w;
            }
            __syncthreads();
            if (kc + 64 < Hdim) {
                const float* p = g_rh + arow * Hdim + (kc + 64) + cbase;
                #pragma unroll
                for (int q = 0; q < 4; q++) hr[q] = reinterpret_cast<const float4*>(p)[q];
            }
            #pragma unroll
            for (int ks = 0; ks < 8; ks++) {
                int k  = ks * 8 + tig;
                int r0 = (wm * 16 + gid) * HSW;
                unsigned a[4] = { Hs[r0 + k], Hs[r0 + 8 * HSW + k],
                                  Hs[r0 + k + 4], Hs[r0 + 8 * HSW + k + 4] };
                int kk = kc + k;
                int n0 = wn * 8 + gid;
                mma8(accB, a, WB[n0 * SW + kk], WB[n0 * SW + kk + 4]);
            }
            __syncthreads();
        }
        {
            const float* __restrict__ xh = g_xg + (2l * Tdim + t) * Bdim * Hdim;
            #pragma unroll
            for (int i = 0; i < 4; i++) {
                int b = wm * 16 + gid + ((i >= 2) ? 8 : 0);
                int j = jbB + wn * 8 + tig * 2 + (i & 1);
                int idx = b * Hdim + j;
                float ht = tanhf(accB[i] + xh[idx]);
                float z  = g_z[idx];
                float h  = g_h[idx];
                float hn = fmaf(z, ht - h, h);   // (1-z)*h + z*ht
                g_h[idx] = hn;
                out[((long)b * Tdim + t) * Hdim + j] = hn;
            }
        }
        grid_barrier(&gen);
    }

    // h_n = final hidden state, appended after (B,T,H)
    {
        float4*       dst = reinterpret_cast<float4*>(out + (long)Bdim * Tdim * Hdim);
        const float4* src = reinterpret_cast<const float4*>(g_h);
        dst[c * 256 + tid] = src[c * 256 + tid];
    }
}

__global__ void init_h(const float* __restrict__ h0) {
    int i = blockIdx.x * blockDim.x + threadIdx.x;
    g_h[i] = h0[i];
}

extern "C" void kernel_launch(void* const* d_in, const int* in_sizes, int n_in,
                              void* d_out, int out_size)
{
    const float* x  = (const float*)d_in[0];
    const float* h0 = (const float*)d_in[1];
    const float* Wz = (const float*)d_in[2];
    const float* bz = (const float*)d_in[3];
    const float* Uz = (const float*)d_in[4];
    const float* Wr = (const float*)d_in[5];
    const float* br = (const float*)d_in[6];
    const float* Ur = (const float*)d_in[7];
    const float* Wh = (const float*)d_in[8];
    const float* bh = (const float*)d_in[9];
    const float* Uh = (const float*)d_in[10];
    float* out = (float*)d_out;

    const int smem_bytes = (32 * SW + 16 * SW + 64 * HSW) * 4;  // 214784 B
    cudaFuncSetAttribute(scan_kernel, cudaFuncAttributeMaxDynamicSharedMemorySize, smem_bytes);

    init_h<<<256, 256>>>(h0);
    proj_kernel<<<dim3(512, 16, 3), 256>>>(x, Wz, bz, Wr, br, Wh, bh);
    scan_kernel<<<NCTA, 256, smem_bytes>>>(Uz, Ur, Uh, out);
}

// round 7
// speedup vs baseline: 1.5097x; 1.5097x over previous
#include <cuda_runtime.h>

// GRU: B=64, T=1024, INPUT=512, HIDDEN=1024
// out = (B,T,H) fp32 followed by h_n = (1,B,H) fp32.

#define Bdim 64
#define Tdim 1024
#define Idim 512
#define Hdim 1024
#define NCTA 128     // persistent scan CTAs (<=148 SMs -> co-resident, 1 CTA/SM)

// ------------------------- device scratch (static; no runtime alloc) -------
static __device__ float g_xg[3ull * Tdim * Bdim * Hdim];  // [gate][t][b][h], bias included
static __device__ float g_h [Bdim * Hdim];
static __device__ float g_z [Bdim * Hdim];
static __device__ float g_rh[Bdim * Hdim];
static __device__ unsigned g_bar_count;   // returns to 0 after every barrier
static __device__ unsigned g_bar_gen;     // monotonic; equality-spin is wrap-safe

__device__ __forceinline__ unsigned f2tf(float f) {
    unsigned u;
    asm("cvt.rna.tf32.f32 %0, %1;" : "=r"(u) : "f"(f));
    return u;
}

// D += A(16x8,row) * B(8x8,col)   tf32 -> f32
__device__ __forceinline__ void mma8(float* d, const unsigned* a, unsigned b0, unsigned b1) {
    asm volatile(
        "mma.sync.aligned.m16n8k8.row.col.f32.tf32.tf32.f32 "
        "{%0,%1,%2,%3}, {%4,%5,%6,%7}, {%8,%9}, {%0,%1,%2,%3};\n"
        : "+f"(d[0]), "+f"(d[1]), "+f"(d[2]), "+f"(d[3])
        : "r"(a[0]), "r"(a[1]), "r"(a[2]), "r"(a[3]), "r"(b0), "r"(b1));
}

// Grid-wide barrier for NCTA co-resident CTAs. Generation-counting; every
// CTA reads g_bar_gen before its first arrival, so the spin value is stable.
__device__ __forceinline__ void grid_barrier(unsigned* gen) {
    __threadfence();
    __syncthreads();
    if (threadIdx.x == 0) {
        unsigned old = atomicAdd(&g_bar_count, 1u);
        if (old == NCTA - 1) {
            atomicExch(&g_bar_count, 0u);
            __threadfence();
            atomicAdd(&g_bar_gen, 1u);
        } else {
            while (*(volatile unsigned*)&g_bar_gen == *gen) {
                __nanosleep(64);
            }
        }
        __threadfence();
    }
    __syncthreads();
    (*gen)++;
}

// ---------------------------------------------------------------------------
// Input projection: for gate g, xg[g][t][b][:] = x[b][t][:] @ W_g^T + b_g
// grid = (48 = gate*16+ny, 512 m-tiles): concurrent CTAs share x tiles in L2.
// ---------------------------------------------------------------------------
__global__ __launch_bounds__(256, 2) void proj_kernel(
    const float* __restrict__ x,
    const float* __restrict__ Wz, const float* __restrict__ bz,
    const float* __restrict__ Wr, const float* __restrict__ br,
    const float* __restrict__ Wh, const float* __restrict__ bh)
{
    const int gate = blockIdx.x >> 4;
    const float* __restrict__ W    = (gate == 0) ? Wz : (gate == 1) ? Wr : Wh;
    const float* __restrict__ bias = (gate == 0) ? bz : (gate == 1) ? br : bh;

    __shared__ unsigned As[128][33];
    __shared__ unsigned Bs[64][33];

    const int tid  = threadIdx.x;
    const int lane = tid & 31;
    const int warp = tid >> 5;
    const int gid  = lane >> 2;
    const int tig  = lane & 3;
    const int wm   = warp >> 1;
    const int wn   = warp & 1;

    const long mbase = (long)blockIdx.y * 128;
    const int  nbase = (blockIdx.x & 15) * 64;

    const int arow = tid >> 1;
    const int aseg = (tid & 1) * 16;
    const int brow = tid >> 3;
    const int bcol = (tid & 7) * 4;

    float acc[2][4][4];
    #pragma unroll
    for (int i = 0; i < 2; i++)
        #pragma unroll
        for (int j = 0; j < 4; j++)
            #pragma unroll
            for (int k = 0; k < 4; k++) acc[i][j][k] = 0.f;

    float4 aR[4], bR[2];
    {
        const float* ap = x + (mbase + arow) * Idim + aseg;
        #pragma unroll
        for (int q = 0; q < 4; q++) aR[q] = reinterpret_cast<const float4*>(ap)[q];
        #pragma unroll
        for (int p = 0; p < 2; p++)
            bR[p] = *reinterpret_cast<const float4*>(W + (long)(nbase + brow + p * 32) * Idim + bcol);
    }

    for (int kc = 0; kc < Idim; kc += 32) {
        #pragma unroll
        for (int q = 0; q < 4; q++) {
            As[arow][aseg + q * 4 + 0] = f2tf(aR[q].x);
            As[arow][aseg + q * 4 + 1] = f2tf(aR[q].y);
            As[arow][aseg + q * 4 + 2] = f2tf(aR[q].z);
            As[arow][aseg + q * 4 + 3] = f2tf(aR[q].w);
        }
        #pragma unroll
        for (int p = 0; p < 2; p++) {
            Bs[brow + p * 32][bcol + 0] = f2tf(bR[p].x);
            Bs[brow + p * 32][bcol + 1] = f2tf(bR[p].y);
            Bs[brow + p * 32][bcol + 2] = f2tf(bR[p].z);
            Bs[brow + p * 32][bcol + 3] = f2tf(bR[p].w);
        }
        __syncthreads();

        if (kc + 32 < Idim) {
            const float* ap = x + (mbase + arow) * Idim + (kc + 32) + aseg;
            #pragma unroll
            for (int q = 0; q < 4; q++) aR[q] = reinterpret_cast<const float4*>(ap)[q];
            #pragma unroll
            for (int p = 0; p < 2; p++)
                bR[p] = *reinterpret_cast<const float4*>(W + (long)(nbase + brow + p * 32) * Idim + (kc + 32) + bcol);
        }

        #pragma unroll
        for (int ks = 0; ks < 4; ks++) {
            unsigned afrag[2][4];
            #pragma unroll
            for (int mt = 0; mt < 2; mt++) {
                int r0 = wm * 32 + mt * 16 + gid;
                afrag[mt][0] = As[r0    ][ks * 8 + tig];
                afrag[mt][1] = As[r0 + 8][ks * 8 + tig];
                afrag[mt][2] = As[r0    ][ks * 8 + tig + 4];
                afrag[mt][3] = As[r0 + 8][ks * 8 + tig + 4];
            }
            #pragma unroll
            for (int nt = 0; nt < 4; nt++) {
                int n0 = wn * 32 + nt * 8 + gid;
                unsigned b0 = Bs[n0][ks * 8 + tig];
                unsigned b1 = Bs[n0][ks * 8 + tig + 4];
                mma8(acc[0][nt], afrag[0], b0, b1);
                mma8(acc[1][nt], afrag[1], b0, b1);
            }
        }
        __syncthreads();
    }

    #pragma unroll
    for (int mt = 0; mt < 2; mt++) {
        #pragma unroll
        for (int nt = 0; nt < 4; nt++) {
            #pragma unroll
            for (int i = 0; i < 4; i++) {
                int mr = wm * 32 + mt * 16 + gid + ((i >= 2) ? 8 : 0);
                int j  = nbase + wn * 32 + nt * 8 + tig * 2 + (i & 1);
                long m = mbase + mr;
                int b = (int)(m >> 10);   // x rows are (b, t), t fastest (T=1024)
                int t = (int)(m & 1023);
                float v = acc[mt][nt][i] + bias[j];
                g_xg[(((long)gate * Tdim + t) * Bdim + b) * Hdim + j] = v;
            }
        }
    }
}

// ---------------------------------------------------------------------------
// Persistent scan: 128 CTAs x 256 threads, weights SMEM-resident in packed
// fragment order. h staged per 64-col chunk in mma-fragment granules (16B,
// XOR-swizzled), double-buffered, 1 syncthreads/chunk.
// Phase A: CTA c<64 -> z cols [16c,16c+16); c>=64 -> r cols. 2 n-blocks/CTA.
// Phase B: CTA c -> h~ cols [8c,8c+8); warp pairs split k-parity, smem-reduce.
// ---------------------------------------------------------------------------
extern __shared__ unsigned smem_u[];

__global__ __launch_bounds__(256, 1) void scan_kernel(
    const float* __restrict__ Uz, const float* __restrict__ Ur,
    const float* __restrict__ Uh, const float* __restrict__ h0,
    float* __restrict__ out)
{
    unsigned* WAp = smem_u;                       // 16384 words (64 KB)
    unsigned* WBp = smem_u + 16384;               //  8192 words (32 KB)
    uint4*    Hp  = (uint4*)(smem_u + 24576);     // 2 bufs x 1024 granules (32 KB)
    float*    red = (float*)(smem_u + 24576);     // reuses Hp buf0 for reduction

    const int c    = blockIdx.x;
    const int tid  = threadIdx.x;
    const int lane = tid & 31;
    const int warp = tid >> 5;
    const int gid  = lane >> 2;
    const int tig  = lane & 3;

    const int gate = c >> 6;
    const int jbA  = (c & 63) * 16;
    const int jbB  = c * 8;
    const float* __restrict__ UA = gate ? Ur : Uz;

    // ---- one-time: pack weight slices into fragment-pair order ----
    // WAp granule (nb, kg, lane): {W[jbA+nb*8+gid][kg*8+tig], W[..][..+4]}
    for (int idx = tid; idx < 8192; idx += 256) {
        int nb = idx >> 12, kg = (idx >> 5) & 127, ln = idx & 31;
        long row = jbA + nb * 8 + (ln >> 2);
        int  k   = kg * 8 + (ln & 3);
        WAp[idx * 2]     = f2tf(UA[row * Hdim + k]);
        WAp[idx * 2 + 1] = f2tf(UA[row * Hdim + k + 4]);
    }
    for (int idx = tid; idx < 4096; idx += 256) {
        int kg = idx >> 5, ln = idx & 31;
        long row = jbB + (ln >> 2);
        int  k   = kg * 8 + (ln & 3);
        WBp[idx * 2]     = f2tf(Uh[row * Hdim + k]);
        WBp[idx * 2 + 1] = f2tf(Uh[row * Hdim + k + 4]);
    }

    unsigned gen = *(volatile unsigned*)&g_bar_gen;  // read before any barrier
    __syncthreads();

    // staging role: thread owns rows (srow, srow+8), cols [cseg*8, cseg*8+8)
    const int sp   = tid >> 3;        // 0..31 row-pair id
    const int ss   = sp >> 3;         // stripe 0..3
    const int sg   = sp & 7;          // row-in-stripe 0..7
    const int cseg = tid & 7;         // k-group within chunk
    const int srow = ss * 16 + sg;

    const int wm = warp >> 1;         // m-stripe 0..3
    const int wn = warp & 1;          // phase A n-block / phase B k-parity

    int idxA[4], idxB[4];
    #pragma unroll
    for (int i = 0; i < 4; i++) {
        int bA = wm * 16 + gid + ((i >= 2) ? 8 : 0);
        idxA[i] = bA * Hdim + jbA + wn * 8 + tig * 2 + (i & 1);
        idxB[i] = bA * Hdim + jbB + tig * 2 + (i & 1);
    }

    float4 f0, f1, f2, f3;

    for (int t = 0; t < Tdim; t++) {
        const float* __restrict__ hsrc = (t == 0) ? h0 : g_h;

        // ============ Phase A: z / r pre-activations ============
        float xpre[4], hpre[4];
        {
            const float* __restrict__ xga = g_xg + ((long)gate * Tdim + t) * (Bdim * Hdim);
            #pragma unroll
            for (int i = 0; i < 4; i++) { xpre[i] = xga[idxA[i]]; hpre[i] = hsrc[idxA[i]]; }
        }

        float acc[4] = {0.f, 0.f, 0.f, 0.f};
        {
            const float* a = hsrc + srow * Hdim + cseg * 8;
            f0 = *(const float4*)(a);            f1 = *(const float4*)(a + 4);
            f2 = *(const float4*)(a + 8 * Hdim); f3 = *(const float4*)(a + 8 * Hdim + 4);
        }
        {   // store chunk 0 into buf 0 (packed + swizzled)
            uint4* b = Hp + (ss * 8 + cseg) * 32;
            b[(sg * 4 + 0) ^ cseg] = make_uint4(f2tf(f0.x), f2tf(f2.x), f2tf(f1.x), f2tf(f3.x));
            b[(sg * 4 + 1) ^ cseg] = make_uint4(f2tf(f0.y), f2tf(f2.y), f2tf(f1.y), f2tf(f3.y));
            b[(sg * 4 + 2) ^ cseg] = make_uint4(f2tf(f0.z), f2tf(f2.z), f2tf(f1.z), f2tf(f3.z));
            b[(sg * 4 + 3) ^ cseg] = make_uint4(f2tf(f0.w), f2tf(f2.w), f2tf(f1.w), f2tf(f3.w));
        }
        __syncthreads();

        for (int i = 0; i < 16; i++) {
            if (i < 15) {
                const float* a = hsrc + srow * Hdim + (i + 1) * 64 + cseg * 8;
                f0 = *(const float4*)(a);            f1 = *(const float4*)(a + 4);
                f2 = *(const float4*)(a + 8 * Hdim); f3 = *(const float4*)(a + 8 * Hdim + 4);
            }
            {
                const uint4* h = Hp + (i & 1) * 1024;
                #pragma unroll
                for (int ks = 0; ks < 8; ks++) {
                    uint4 a4 = h[(wm * 8 + ks) * 32 + (lane ^ ks)];
                    unsigned av[4] = {a4.x, a4.y, a4.z, a4.w};
                    uint2 bv = ((const uint2*)WAp)[(wn * 128 + i * 8 + ks) * 32 + lane];
                    mma8(acc, av, bv.x, bv.y);
                }
            }
            if (i < 15) {
                uint4* b = Hp + ((i + 1) & 1) * 1024 + (ss * 8 + cseg) * 32;
                b[(sg * 4 + 0) ^ cseg] = make_uint4(f2tf(f0.x), f2tf(f2.x), f2tf(f1.x), f2tf(f3.x));
                b[(sg * 4 + 1) ^ cseg] = make_uint4(f2tf(f0.y), f2tf(f2.y), f2tf(f1.y), f2tf(f3.y));
                b[(sg * 4 + 2) ^ cseg] = make_uint4(f2tf(f0.z), f2tf(f2.z), f2tf(f1.z), f2tf(f3.z));
                b[(sg * 4 + 3) ^ cseg] = make_uint4(f2tf(f0.w), f2tf(f2.w), f2tf(f1.w), f2tf(f3.w));
            }
            __syncthreads();
        }

        #pragma unroll
        for (int i = 0; i < 4; i++) {
            float pre = acc[i] + xpre[i];
            float s = 1.0f / (1.0f + __expf(-pre));
            if (gate == 0) g_z[idxA[i]] = s;
            else           g_rh[idxA[i]] = s * hpre[i];
        }
        grid_barrier(&gen);

        // ============ Phase B: h_tilde + state update ============
        float xh[4], zv[4], hv[4];
        if (wn == 0) {
            const float* __restrict__ xhb = g_xg + (2l * Tdim + t) * (Bdim * Hdim);
            #pragma unroll
            for (int i = 0; i < 4; i++) {
                xh[i] = xhb[idxB[i]]; zv[i] = g_z[idxB[i]]; hv[i] = hsrc[idxB[i]];
            }
        }

        float accB[4] = {0.f, 0.f, 0.f, 0.f};
        {
            const float* a = g_rh + srow * Hdim + cseg * 8;
            f0 = *(const float4*)(a);            f1 = *(const float4*)(a + 4);
            f2 = *(const float4*)(a + 8 * Hdim); f3 = *(const float4*)(a + 8 * Hdim + 4);
        }
        {
            uint4* b = Hp + (ss * 8 + cseg) * 32;
            b[(sg * 4 + 0) ^ cseg] = make_uint4(f2tf(f0.x), f2tf(f2.x), f2tf(f1.x), f2tf(f3.x));
            b[(sg * 4 + 1) ^ cseg] = make_uint4(f2tf(f0.y), f2tf(f2.y), f2tf(f1.y), f2tf(f3.y));
            b[(sg * 4 + 2) ^ cseg] = make_uint4(f2tf(f0.z), f2tf(f2.z), f2tf(f1.z), f2tf(f3.z));
            b[(sg * 4 + 3) ^ cseg] = make_uint4(f2tf(f0.w), f2tf(f2.w), f2tf(f1.w), f2tf(f3.w));
        }
        __syncthreads();

        for (int i = 0; i < 16; i++) {
            if (i < 15) {
                const float* a = g_rh + srow * Hdim + (i + 1) * 64 + cseg * 8;
                f0 = *(const float4*)(a);            f1 = *(const float4*)(a + 4);
                f2 = *(const float4*)(a + 8 * Hdim); f3 = *(const float4*)(a + 8 * Hdim + 4);
            }
            {
                const uint4* h = Hp + (i & 1) * 1024;
                #pragma unroll
                for (int jk = 0; jk < 4; jk++) {
                    int ks = jk * 2 + wn;   // k-parity split across warp pairs
                    uint4 a4 = h[(wm * 8 + ks) * 32 + (lane ^ ks)];
                    unsigned av[4] = {a4.x, a4.y, a4.z, a4.w};
                    uint2 bv = ((const uint2*)WBp)[(i * 8 + ks) * 32 + lane];
                    mma8(accB, av, bv.x, bv.y);
                }
            }
            if (i < 15) {
                uint4* b = Hp + ((i + 1) & 1) * 1024 + (ss * 8 + cseg) * 32;
                b[(sg * 4 + 0) ^ cseg] = make_uint4(f2tf(f0.x), f2tf(f2.x), f2tf(f1.x), f2tf(f3.x));
                b[(sg * 4 + 1) ^ cseg] = make_uint4(f2tf(f0.y), f2tf(f2.y), f2tf(f1.y), f2tf(f3.y));
                b[(sg * 4 + 2) ^ cseg] = make_uint4(f2tf(f0.z), f2tf(f2.z), f2tf(f1.z), f2tf(f3.z));
                b[(sg * 4 + 3) ^ cseg] = make_uint4(f2tf(f0.w), f2tf(f2.w), f2tf(f1.w), f2tf(f3.w));
            }
            __syncthreads();
        }

        // pairwise k-parity reduction (reuses Hp buf0; guarded by syncs)
        if (wn == 1) {
            #pragma unroll
            for (int i = 0; i < 4; i++) red[(wm * 32 + lane) * 4 + i] = accB[i];
        }
        __syncthreads();
        if (wn == 0) {
            #pragma unroll
            for (int i = 0; i < 4; i++) {
                float pre = accB[i] + red[(wm * 32 + lane) * 4 + i] + xh[i];
                float ht = tanhf(pre);
                float hn = fmaf(zv[i], ht - hv[i], hv[i]);   // (1-z)*h + z*ht
                g_h[idxB[i]] = hn;
                int b = idxB[i] >> 10, j = idxB[i] & 1023;
                out[((long)b * Tdim + t) * Hdim + j] = hn;
            }
        }
        grid_barrier(&gen);
    }

    // h_n = final hidden state, appended after (B,T,H)
    {
        float2*       dst = reinterpret_cast<float2*>(out + (long)Bdim * Tdim * Hdim);
        const float2* src = reinterpret_cast<const float2*>(g_h);
        dst[c * 256 + tid] = src[c * 256 + tid];
    }
}

extern "C" void kernel_launch(void* const* d_in, const int* in_sizes, int n_in,
                              void* d_out, int out_size)
{
    const float* x  = (const float*)d_in[0];
    const float* h0 = (const float*)d_in[1];
    const float* Wz = (const float*)d_in[2];
    const float* bz = (const float*)d_in[3];
    const float* Uz = (const float*)d_in[4];
    const float* Wr = (const float*)d_in[5];
    const float* br = (const float*)d_in[6];
    const float* Ur = (const float*)d_in[7];
    const float* Wh = (const float*)d_in[8];
    const float* bh = (const float*)d_in[9];
    const float* Uh = (const float*)d_in[10];
    float* out = (float*)d_out;

    const int smem_bytes = 32768 * 4;  // 131072 B
    cudaFuncSetAttribute(scan_kernel, cudaFuncAttributeMaxDynamicSharedMemorySize, smem_bytes);

    proj_kernel<<<dim3(48, 512), 256>>>(x, Wz, bz, Wr, br, Wh, bh);
    scan_kernel<<<NCTA, 256, smem_bytes>>>(Uz, Ur, Uh, h0, out);
}

// round 8
// speedup vs baseline: 2.9998x; 1.9871x over previous
#include <cuda_runtime.h>
#include <cuda_fp16.h>

// GRU: B=64, T=1024, INPUT=512, HIDDEN=1024
// out = (B,T,H) fp32 followed by h_n = (1,B,H) fp32.

#define Bdim 64
#define Tdim 1024
#define Idim 512
#define Hdim 1024
#define NCTA 64
#define BH   (Bdim * Hdim)

// ------------------------- device scratch (static; no runtime alloc) -------
static __device__ float g_xg[3ull * Tdim * Bdim * Hdim];  // [gate][t][b][h], bias included
// Fragment-ordered state (granule = (K,s): 32 lanes x 16B; K=k/16, s=b/16):
static __device__ uint4  g_h16 [64 * 4 * 32];   // h as fp16 mma-A fragments (128KB)
static __device__ uint4  g_rh16[64 * 4 * 32];   // r*h as fp16 mma-A fragments
// Fragment-ordered fp32 (float4 = {v[r][j0],v[r][j0+1],v[r+8][j0],v[r+8][j0+1]}, cb=j>>3):
static __device__ float4 g_h4[128 * 4 * 32];    // h fp32 (256KB)
static __device__ float4 g_z4[128 * 4 * 32];    // z fp32
static __device__ unsigned g_flags[NCTA];       // barrier arrival tokens (monotonic)
static __device__ unsigned g_bar_gen;           // barrier release token (monotonic)

__device__ __forceinline__ unsigned f2tf(float f) {
    unsigned u;
    asm("cvt.rna.tf32.f32 %0, %1;" : "=r"(u) : "f"(f));
    return u;
}
__device__ __forceinline__ unsigned packh2(float a, float b) {
    __half2 h = __floats2half2_rn(a, b);
    return *reinterpret_cast<unsigned*>(&h);
}
__device__ __forceinline__ float sigf(float x) { return 1.0f / (1.0f + __expf(-x)); }

// D += A(16x8,row) * B(8x8,col)   tf32 (proj kernel)
__device__ __forceinline__ void mma8(float* d, const unsigned* a, unsigned b0, unsigned b1) {
    asm volatile(
        "mma.sync.aligned.m16n8k8.row.col.f32.tf32.tf32.f32 "
        "{%0,%1,%2,%3}, {%4,%5,%6,%7}, {%8,%9}, {%0,%1,%2,%3};\n"
        : "+f"(d[0]), "+f"(d[1]), "+f"(d[2]), "+f"(d[3])
        : "r"(a[0]), "r"(a[1]), "r"(a[2]), "r"(a[3]), "r"(b0), "r"(b1));
}
// D += A(16x16,row) * B(16x8,col)  fp16 -> fp32 (scan kernel)
__device__ __forceinline__ void mma16(float* d, const uint4 a, const uint2 b) {
    asm volatile(
        "mma.sync.aligned.m16n8k16.row.col.f32.f16.f16.f32 "
        "{%0,%1,%2,%3}, {%4,%5,%6,%7}, {%8,%9}, {%0,%1,%2,%3};\n"
        : "+f"(d[0]), "+f"(d[1]), "+f"(d[2]), "+f"(d[3])
        : "r"(a.x), "r"(a.y), "r"(a.z), "r"(a.w), "r"(b.x), "r"(b.y));
}

// Flag-array grid barrier: parallel arrivals, CTA0 polls, publishes token.
__device__ __forceinline__ void gbar(unsigned token, int c) {
    __syncthreads();
    if (threadIdx.x == 0) { __threadfence(); __stcg(&g_flags[c], token); }
    if (c == 0) {
        if (threadIdx.x < NCTA) {
            while ((int)(__ldcg(&g_flags[threadIdx.x]) - token) < 0) __nanosleep(32);
        }
        __syncthreads();
        if (threadIdx.x == 0) { __threadfence(); __stcg(&g_bar_gen, token); }
    }
    if (threadIdx.x == 0) {
        while ((int)(__ldcg(&g_bar_gen) - token) < 0) __nanosleep(32);
    }
    __syncthreads();
}

// ---------------------------------------------------------------------------
// init: h0 -> g_h16 (fp16 fragment order) and g_h4 (fp32 fragment order)
// ---------------------------------------------------------------------------
__global__ void init_kernel(const float* __restrict__ h0) {
    int i = blockIdx.x * blockDim.x + threadIdx.x;   // 0..32767 = (b, jpair)
    int b = i >> 9, jp = i & 511;
    float v0 = h0[b * Hdim + 2 * jp], v1 = h0[b * Hdim + 2 * jp + 1];
    int s = b >> 4, r = b & 15, gid = r & 7, hi = r >> 3;
    int K = jp >> 3, p16hi = (jp >> 2) & 1, tig = jp & 3;
    ((unsigned*)g_h16)[(((K * 4 + s) * 32 + gid * 4 + tig) * 4) + (p16hi * 2 + hi)] = packh2(v0, v1);
    int cb = jp >> 2;
    ((float2*)g_h4)[(((cb * 4 + s) * 32 + gid * 4 + tig) * 2) + hi] = make_float2(v0, v1);
}

// ---------------------------------------------------------------------------
// Input projection (tf32): xg[g][t][b][:] = x[b][t][:] @ W_g^T + b_g
// ---------------------------------------------------------------------------
__global__ __launch_bounds__(256, 2) void proj_kernel(
    const float* __restrict__ x,
    const float* __restrict__ Wz, const float* __restrict__ bz,
    const float* __restrict__ Wr, const float* __restrict__ br,
    const float* __restrict__ Wh, const float* __restrict__ bh)
{
    const int gate = blockIdx.x >> 4;
    const float* __restrict__ W    = (gate == 0) ? Wz : (gate == 1) ? Wr : Wh;
    const float* __restrict__ bias = (gate == 0) ? bz : (gate == 1) ? br : bh;

    __shared__ unsigned As[128][33];
    __shared__ unsigned Bs[64][33];

    const int tid  = threadIdx.x;
    const int lane = tid & 31;
    const int warp = tid >> 5;
    const int gid  = lane >> 2;
    const int tig  = lane & 3;
    const int wm   = warp >> 1;
    const int wn   = warp & 1;

    const long mbase = (long)blockIdx.y * 128;
    const int  nbase = (blockIdx.x & 15) * 64;

    const int arow = tid >> 1;
    const int aseg = (tid & 1) * 16;
    const int brow = tid >> 3;
    const int bcol = (tid & 7) * 4;

    float acc[2][4][4];
    #pragma unroll
    for (int i = 0; i < 2; i++)
        #pragma unroll
        for (int j = 0; j < 4; j++)
            #pragma unroll
            for (int k = 0; k < 4; k++) acc[i][j][k] = 0.f;

    float4 aR[4], bR[2];
    {
        const float* ap = x + (mbase + arow) * Idim + aseg;
        #pragma unroll
        for (int q = 0; q < 4; q++) aR[q] = reinterpret_cast<const float4*>(ap)[q];
        #pragma unroll
        for (int p = 0; p < 2; p++)
            bR[p] = *reinterpret_cast<const float4*>(W + (long)(nbase + brow + p * 32) * Idim + bcol);
    }

    for (int kc = 0; kc < Idim; kc += 32) {
        #pragma unroll
        for (int q = 0; q < 4; q++) {
            As[arow][aseg + q * 4 + 0] = f2tf(aR[q].x);
            As[arow][aseg + q * 4 + 1] = f2tf(aR[q].y);
            As[arow][aseg + q * 4 + 2] = f2tf(aR[q].z);
            As[arow][aseg + q * 4 + 3] = f2tf(aR[q].w);
        }
        #pragma unroll
        for (int p = 0; p < 2; p++) {
            Bs[brow + p * 32][bcol + 0] = f2tf(bR[p].x);
            Bs[brow + p * 32][bcol + 1] = f2tf(bR[p].y);
            Bs[brow + p * 32][bcol + 2] = f2tf(bR[p].z);
            Bs[brow + p * 32][bcol + 3] = f2tf(bR[p].w);
        }
        __syncthreads();

        if (kc + 32 < Idim) {
            const float* ap = x + (mbase + arow) * Idim + (kc + 32) + aseg;
            #pragma unroll
            for (int q = 0; q < 4; q++) aR[q] = reinterpret_cast<const float4*>(ap)[q];
            #pragma unroll
            for (int p = 0; p < 2; p++)
                bR[p] = *reinterpret_cast<const float4*>(W + (long)(nbase + brow + p * 32) * Idim + (kc + 32) + bcol);
        }

        #pragma unroll
        for (int ks = 0; ks < 4; ks++) {
            unsigned afrag[2][4];
            #pragma unroll
            for (int mt = 0; mt < 2; mt++) {
                int r0 = wm * 32 + mt * 16 + gid;
                afrag[mt][0] = As[r0    ][ks * 8 + tig];
                afrag[mt][1] = As[r0 + 8][ks * 8 + tig];
                afrag[mt][2] = As[r0    ][ks * 8 + tig + 4];
                afrag[mt][3] = As[r0 + 8][ks * 8 + tig + 4];
            }
            #pragma unroll
            for (int nt = 0; nt < 4; nt++) {
                int n0 = wn * 32 + nt * 8 + gid;
                unsigned b0 = Bs[n0][ks * 8 + tig];
                unsigned b1 = Bs[n0][ks * 8 + tig + 4];
                mma8(acc[0][nt], afrag[0], b0, b1);
                mma8(acc[1][nt], afrag[1], b0, b1);
            }
        }
        __syncthreads();
    }

    #pragma unroll
    for (int mt = 0; mt < 2; mt++) {
        #pragma unroll
        for (int nt = 0; nt < 4; nt++) {
            #pragma unroll
            for (int i = 0; i < 4; i++) {
                int mr = wm * 32 + mt * 16 + gid + ((i >= 2) ? 8 : 0);
                int j  = nbase + wn * 32 + nt * 8 + tig * 2 + (i & 1);
                long m = mbase + mr;
                int b = (int)(m >> 10);   // x rows are (b, t), t fastest
                int t = (int)(m & 1023);
                float v = acc[mt][nt][i] + bias[j];
                g_xg[(((long)gate * Tdim + t) * Bdim + b) * Hdim + j] = v;
            }
        }
    }
}

// ---------------------------------------------------------------------------
// Persistent scan: 64 CTAs x 512 threads (16 warps = 4 stripes x 4 k-quarters).
// CTA c owns hidden cols [16c, 16c+16) for z, r AND h~.
// A-operands (h / r*h) are fp16 fragment-ordered in global: direct LDG.128,
// zero smem staging, zero k-loop syncs. Weights pre-packed B-fragments in smem.
// ---------------------------------------------------------------------------
extern __shared__ unsigned char smem_raw[];

__global__ __launch_bounds__(512, 1) void scan_kernel(
    const float* __restrict__ Uz, const float* __restrict__ Ur,
    const float* __restrict__ Uh, float* __restrict__ out)
{
    uint2*  WA  = (uint2*)smem_raw;                  // [(g*2+nb)*64+K]*32+lane  (64KB)
    uint2*  WB  = (uint2*)(smem_raw + 65536);        // [nb*64+K]*32+lane        (32KB)
    float4* red = (float4*)(smem_raw + 98304);       // k-quarter reduction      (24KB)

    const int c    = blockIdx.x;
    const int tid  = threadIdx.x;
    const int lane = tid & 31;
    const int warp = tid >> 5;
    const int gid  = lane >> 2;
    const int tig  = lane & 3;
    const int s    = warp & 3;     // batch stripe (16 rows)
    const int kq   = warp >> 2;    // k quarter (16 ksteps of 16)

    // ---- one-time: pack weight slices into fp16 B-fragment granules ----
    for (int idx = tid; idx < 4 * 64 * 32; idx += 512) {
        int ln = idx & 31, K = (idx >> 5) & 63, gnb = idx >> 11;
        const float* Ug = (gnb < 2) ? Uz : Ur;
        const float* rp = Ug + (long)(16 * c + (gnb & 1) * 8 + (ln >> 2)) * Hdim + 16 * K + 2 * (ln & 3);
        WA[idx] = make_uint2(packh2(rp[0], rp[1]), packh2(rp[8], rp[9]));
    }
    for (int idx = tid; idx < 2 * 64 * 32; idx += 512) {
        int ln = idx & 31, K = (idx >> 5) & 63, nb = idx >> 11;
        const float* rp = Uh + (long)(16 * c + nb * 8 + (ln >> 2)) * Hdim + 16 * K + 2 * (ln & 3);
        WB[idx] = make_uint2(packh2(rp[0], rp[1]), packh2(rp[8], rp[9]));
    }

    unsigned token = __ldcg(&g_bar_gen);   // replay-safe base (read before any barrier)
    __syncthreads();

    const int b0r = s * 16 + gid;          // epilogue row (kq==0 threads)
    const int j0  = 16 * c + 2 * tig;      // epilogue col pair base

    for (int t = 0; t < Tdim; t++) {
        // ================= Phase A: z and r =================
        float2 xz0a, xz0b, xz1a, xz1b, xr0a, xr0b, xr1a, xr1b;
        float4 h4a, h4b;
        if (kq == 0) {   // prefetch epilogue operands (hidden behind k-loop)
            const float* xzb = g_xg + (long)t * BH;
            const float* xrb = g_xg + ((long)Tdim + t) * BH;
            xz0a = __ldcg((const float2*)(xzb + (long)b0r * Hdim + j0));
            xz0b = __ldcg((const float2*)(xzb + (long)(b0r + 8) * Hdim + j0));
            xz1a = __ldcg((const float2*)(xzb + (long)b0r * Hdim + j0 + 8));
            xz1b = __ldcg((const float2*)(xzb + (long)(b0r + 8) * Hdim + j0 + 8));
            xr0a = __ldcg((const float2*)(xrb + (long)b0r * Hdim + j0));
            xr0b = __ldcg((const float2*)(xrb + (long)(b0r + 8) * Hdim + j0));
            xr1a = __ldcg((const float2*)(xrb + (long)b0r * Hdim + j0 + 8));
            xr1b = __ldcg((const float2*)(xrb + (long)(b0r + 8) * Hdim + j0 + 8));
            h4a  = __ldcg(&g_h4[((c * 2 + 0) * 4 + s) * 32 + lane]);
            h4b  = __ldcg(&g_h4[((c * 2 + 1) * 4 + s) * 32 + lane]);
        }

        float az0[4] = {0,0,0,0}, az1[4] = {0,0,0,0};
        float ar0[4] = {0,0,0,0}, ar1[4] = {0,0,0,0};
        {
            const uint4* Ag = g_h16 + (kq * 16 * 4 + s) * 32 + lane;
            uint4 abuf[4];
            #pragma unroll
            for (int i = 0; i < 4; i++) abuf[i] = __ldcg(Ag + i * 128);
            const uint2* W0 = WA + (kq * 16) * 32 + lane;
            #pragma unroll
            for (int kk = 0; kk < 16; kk++) {
                uint4 av = abuf[kk & 3];
                if (kk < 12) abuf[kk & 3] = __ldcg(Ag + (kk + 4) * 128);
                const uint2* w = W0 + kk * 32;
                uint2 bz0 = w[0], bz1 = w[2048], br0 = w[4096], br1 = w[6144];
                mma16(az0, av, bz0); mma16(az1, av, bz1);
                mma16(ar0, av, br0); mma16(ar1, av, br1);
            }
        }
        if (kq > 0) {
            float4* r = red + (((kq - 1) * 4 + s) * 32 + lane) * 4;
            r[0] = *(float4*)az0; r[1] = *(float4*)az1;
            r[2] = *(float4*)ar0; r[3] = *(float4*)ar1;
        }
        __syncthreads();
        if (kq == 0) {
            #pragma unroll
            for (int e = 0; e < 3; e++) {
                const float4* r = red + ((e * 4 + s) * 32 + lane) * 4;
                float4 v0 = r[0], v1 = r[1], v2 = r[2], v3 = r[3];
                az0[0] += v0.x; az0[1] += v0.y; az0[2] += v0.z; az0[3] += v0.w;
                az1[0] += v1.x; az1[1] += v1.y; az1[2] += v1.z; az1[3] += v1.w;
                ar0[0] += v2.x; ar0[1] += v2.y; ar0[2] += v2.z; ar0[3] += v2.w;
                ar1[0] += v3.x; ar1[1] += v3.y; ar1[2] += v3.z; ar1[3] += v3.w;
            }
            float4 z0 = make_float4(sigf(az0[0] + xz0a.x), sigf(az0[1] + xz0a.y),
                                    sigf(az0[2] + xz0b.x), sigf(az0[3] + xz0b.y));
            float4 z1 = make_float4(sigf(az1[0] + xz1a.x), sigf(az1[1] + xz1a.y),
                                    sigf(az1[2] + xz1b.x), sigf(az1[3] + xz1b.y));
            __stcg(&g_z4[((c * 2 + 0) * 4 + s) * 32 + lane], z0);
            __stcg(&g_z4[((c * 2 + 1) * 4 + s) * 32 + lane], z1);
            float r00 = sigf(ar0[0] + xr0a.x) * h4a.x, r01 = sigf(ar0[1] + xr0a.y) * h4a.y;
            float r02 = sigf(ar0[2] + xr0b.x) * h4a.z, r03 = sigf(ar0[3] + xr0b.y) * h4a.w;
            float r10 = sigf(ar1[0] + xr1a.x) * h4b.x, r11 = sigf(ar1[1] + xr1a.y) * h4b.y;
            float r12 = sigf(ar1[2] + xr1b.x) * h4b.z, r13 = sigf(ar1[3] + xr1b.y) * h4b.w;
            uint4 rg = make_uint4(packh2(r00, r01), packh2(r02, r03),
                                  packh2(r10, r11), packh2(r12, r13));
            __stcg(&g_rh16[(c * 4 + s) * 32 + lane], rg);
        }
        token++; gbar(token, c);

        // ================= Phase B: h_tilde + update =================
        float2 xh0a, xh0b, xh1a, xh1b;
        float4 zz0, zz1, hh0, hh1;
        if (kq == 0) {
            const float* xhb = g_xg + (2l * Tdim + t) * BH;
            xh0a = __ldcg((const float2*)(xhb + (long)b0r * Hdim + j0));
            xh0b = __ldcg((const float2*)(xhb + (long)(b0r + 8) * Hdim + j0));
            xh1a = __ldcg((const float2*)(xhb + (long)b0r * Hdim + j0 + 8));
            xh1b = __ldcg((const float2*)(xhb + (long)(b0r + 8) * Hdim + j0 + 8));
            zz0  = __ldcg(&g_z4[((c * 2 + 0) * 4 + s) * 32 + lane]);
            zz1  = __ldcg(&g_z4[((c * 2 + 1) * 4 + s) * 32 + lane]);
            hh0  = __ldcg(&g_h4[((c * 2 + 0) * 4 + s) * 32 + lane]);
            hh1  = __ldcg(&g_h4[((c * 2 + 1) * 4 + s) * 32 + lane]);
        }

        float ab0[4] = {0,0,0,0}, ab1[4] = {0,0,0,0};
        {
            const uint4* Ag = g_rh16 + (kq * 16 * 4 + s) * 32 + lane;
            uint4 abuf[4];
            #pragma unroll
            for (int i = 0; i < 4; i++) abuf[i] = __ldcg(Ag + i * 128);
            const uint2* W0 = WB + (kq * 16) * 32 + lane;
            #pragma unroll
            for (int kk = 0; kk < 16; kk++) {
                uint4 av = abuf[kk & 3];
                if (kk < 12) abuf[kk & 3] = __ldcg(Ag + (kk + 4) * 128);
                const uint2* w = W0 + kk * 32;
                uint2 b0 = w[0], b1 = w[2048];
                mma16(ab0, av, b0); mma16(ab1, av, b1);
            }
        }
        if (kq > 0) {
            float4* r = red + (((kq - 1) * 4 + s) * 32 + lane) * 4;
            r[0] = *(float4*)ab0; r[1] = *(float4*)ab1;
        }
        __syncthreads();
        if (kq == 0) {
            #pragma unroll
            for (int e = 0; e < 3; e++) {
                const float4* r = red + ((e * 4 + s) * 32 + lane) * 4;
                float4 v0 = r[0], v1 = r[1];
                ab0[0] += v0.x; ab0[1] += v0.y; ab0[2] += v0.z; ab0[3] += v0.w;
                ab1[0] += v1.x; ab1[1] += v1.y; ab1[2] += v1.z; ab1[3] += v1.w;
            }
            float ht00 = tanhf(ab0[0] + xh0a.x), ht01 = tanhf(ab0[1] + xh0a.y);
            float ht02 = tanhf(ab0[2] + xh0b.x), ht03 = tanhf(ab0[3] + xh0b.y);
            float ht10 = tanhf(ab1[0] + xh1a.x), ht11 = tanhf(ab1[1] + xh1a.y);
            float ht12 = tanhf(ab1[2] + xh1b.x), ht13 = tanhf(ab1[3] + xh1b.y);
            float hn00 = fmaf(zz0.x, ht00 - hh0.x, hh0.x);
            float hn01 = fmaf(zz0.y, ht01 - hh0.y, hh0.y);
            float hn02 = fmaf(zz0.z, ht02 - hh0.z, hh0.z);
            float hn03 = fmaf(zz0.w, ht03 - hh0.w, hh0.w);
            float hn10 = fmaf(zz1.x, ht10 - hh1.x, hh1.x);
            float hn11 = fmaf(zz1.y, ht11 - hh1.y, hh1.y);
            float hn12 = fmaf(zz1.z, ht12 - hh1.z, hh1.z);
            float hn13 = fmaf(zz1.w, ht13 - hh1.w, hh1.w);
            __stcg(&g_h4[((c * 2 + 0) * 4 + s) * 32 + lane], make_float4(hn00, hn01, hn02, hn03));
            __stcg(&g_h4[((c * 2 + 1) * 4 + s) * 32 + lane], make_float4(hn10, hn11, hn12, hn13));
            __stcg(&g_h16[(c * 4 + s) * 32 + lane],
                   make_uint4(packh2(hn00, hn01), packh2(hn02, hn03),
                              packh2(hn10, hn11), packh2(hn12, hn13)));
            __stcg((float2*)(out + ((long)b0r * Tdim + t) * Hdim + j0),           make_float2(hn00, hn01));
            __stcg((float2*)(out + ((long)(b0r + 8) * Tdim + t) * Hdim + j0),     make_float2(hn02, hn03));
            __stcg((float2*)(out + ((long)b0r * Tdim + t) * Hdim + j0 + 8),       make_float2(hn10, hn11));
            __stcg((float2*)(out + ((long)(b0r + 8) * Tdim + t) * Hdim + j0 + 8), make_float2(hn12, hn13));
            if (t == Tdim - 1) {
                float* tail = out + (long)Bdim * Tdim * Hdim;
                *(float2*)(tail + b0r * Hdim + j0)           = make_float2(hn00, hn01);
                *(float2*)(tail + (b0r + 8) * Hdim + j0)     = make_float2(hn02, hn03);
                *(float2*)(tail + b0r * Hdim + j0 + 8)       = make_float2(hn10, hn11);
                *(float2*)(tail + (b0r + 8) * Hdim + j0 + 8) = make_float2(hn12, hn13);
            }
        }
        token++; gbar(token, c);
    }
}

extern "C" void kernel_launch(void* const* d_in, const int* in_sizes, int n_in,
                              void* d_out, int out_size)
{
    const float* x  = (const float*)d_in[0];
    const float* h0 = (const float*)d_in[1];
    const float* Wz = (const float*)d_in[2];
    const float* bz = (const float*)d_in[3];
    const float* Uz = (const float*)d_in[4];
    const float* Wr = (const float*)d_in[5];
    const float* br = (const float*)d_in[6];
    const float* Ur = (const float*)d_in[7];
    const float* Wh = (const float*)d_in[8];
    const float* bh = (const float*)d_in[9];
    const float* Uh = (const float*)d_in[10];
    float* out = (float*)d_out;

    const int smem_bytes = 65536 + 32768 + 24576;  // 122880 B
    cudaFuncSetAttribute(scan_kernel, cudaFuncAttributeMaxDynamicSharedMemorySize, smem_bytes);

    init_kernel<<<128, 256>>>(h0);
    proj_kernel<<<dim3(48, 512), 256>>>(x, Wz, bz, Wr, br, Wh, bh);
    scan_kernel<<<NCTA, 512, smem_bytes>>>(Uz, Ur, Uh, out);
}